// round 9
// baseline (speedup 1.0000x reference)
#include <cuda_runtime.h>
#include <cstddef>

#define BB   16
#define NN   8192
#define SS   1024        // NPOINT
#define KK   32          // NSAMPLE
#define DD   9
#define MCOL (BB*SS*KK)  // 524288 columns
#define NBLKMAX 4096     // g_ps leading stride
#define NBLK1 4096       // gemm1/2 blocks (128-wide tiles)
#define NBLK0 2048       // merged bq+gemm0 blocks

// ---------------- device scratch (static: no cudaMalloc allowed) ----------------
__device__ float  g_Y0[(size_t)64  * MCOL];   // layer0 raw out
__device__ float  g_Y1[(size_t)64  * MCOL];   // layer1 raw out
__device__ float  g_P2[(size_t)BB * SS * 128];// layer2 pooled raw max  [ms][c]
__device__ int    g_cent[BB * SS];
__device__ double g_ps [(size_t)128 * NBLKMAX];
__device__ double g_pss[(size_t)128 * NBLKMAX];
__device__ float  g_scl[3][128];
__device__ float  g_shf[3][128];

// ---------------- f32x2 packed helpers (sm_100+) ----------------
__device__ __forceinline__ unsigned long long pack2(float a, float b) {
    unsigned long long r;
    asm("mov.b64 %0, {%1, %2};" : "=l"(r) : "f"(a), "f"(b));
    return r;
}
__device__ __forceinline__ void unpack2(unsigned long long v, float& a, float& b) {
    asm("mov.b64 {%0, %1}, %2;" : "=f"(a), "=f"(b) : "l"(v));
}
__device__ __forceinline__ unsigned long long add2(unsigned long long a, unsigned long long b) {
    unsigned long long r;
    asm("add.rn.f32x2 %0, %1, %2;" : "=l"(r) : "l"(a), "l"(b));
    return r;
}
__device__ __forceinline__ unsigned long long mul2(unsigned long long a, unsigned long long b) {
    unsigned long long r;
    asm("mul.rn.f32x2 %0, %1, %2;" : "=l"(r) : "l"(a), "l"(b));
    return r;
}
__device__ __forceinline__ unsigned long long fma2(unsigned long long a, unsigned long long b, unsigned long long c) {
    unsigned long long r;
    asm("fma.rn.f32x2 %0, %1, %2, %3;" : "=l"(r) : "l"(a), "l"(b), "l"(c));
    return r;
}

// ---------------- FPS (R5-exact): f32x2 math + REDUX argmax ----------------
// d = fma(dz,dz, fma(dy,dy, dx*dx)) with dx = x + (-cx)  (== x - cx exactly)
__global__ __launch_bounds__(1024) void fps_kernel(const float* __restrict__ xyz)
{
    extern __shared__ float sh[];
    float* sx = sh;
    float* sy = sh + NN;
    float* sz = sh + 2 * NN;
    __shared__ unsigned bufv[2][32];
    __shared__ unsigned bufi[2][32];

    int b = blockIdx.x, t = threadIdx.x;
    int lane = t & 31, w = t >> 5;
    const float* xb = xyz + (size_t)b * NN * 3;

    float xs[8], ys[8], zs[8], Dst[8];
#pragma unroll
    for (int j = 0; j < 8; j++) {
        int p = j * 1024 + t;
        xs[j] = xb[p * 3 + 0];
        ys[j] = xb[p * 3 + 1];
        zs[j] = xb[p * 3 + 2];
        Dst[j] = 1e10f;
        sx[p] = xs[j]; sy[p] = ys[j]; sz[p] = zs[j];
    }
    unsigned long long X2[4], Y2[4], Z2[4];
#pragma unroll
    for (int jp = 0; jp < 4; jp++) {
        X2[jp] = pack2(xs[2 * jp], xs[2 * jp + 1]);
        Y2[jp] = pack2(ys[2 * jp], ys[2 * jp + 1]);
        Z2[jp] = pack2(zs[2 * jp], zs[2 * jp + 1]);
    }
    if (t == 0) g_cent[b * SS] = 0;
    int far = 0, par = 0;
    __syncthreads();

    for (int it = 1; it < SS; ++it) {
        float cx = sx[far], cy = sy[far], cz = sz[far];
        unsigned long long cx2 = pack2(-cx, -cx);
        unsigned long long cy2 = pack2(-cy, -cy);
        unsigned long long cz2 = pack2(-cz, -cz);
        float bv = -1.0f; int bi = 0;
#pragma unroll
        for (int jp = 0; jp < 4; jp++) {
            unsigned long long dx2 = add2(X2[jp], cx2);
            unsigned long long dy2 = add2(Y2[jp], cy2);
            unsigned long long dz2 = add2(Z2[jp], cz2);
            unsigned long long d2 = fma2(dz2, dz2, fma2(dy2, dy2, mul2(dx2, dx2)));
            float dlo, dhi;
            unpack2(d2, dlo, dhi);
            float nlo = fminf(Dst[2 * jp], dlo);
            float nhi = fminf(Dst[2 * jp + 1], dhi);
            Dst[2 * jp] = nlo;
            Dst[2 * jp + 1] = nhi;
            if (nlo > bv) { bv = nlo; bi = 2 * jp * 1024 + t; }       // ascending p
            if (nhi > bv) { bv = nhi; bi = (2 * jp + 1) * 1024 + t; } // strict > keeps first
        }
        // warp argmax via REDUX (d >= 0 so float bits are order-preserving)
        unsigned vb = __float_as_uint(bv);
        unsigned m1 = __reduce_max_sync(0xffffffffu, vb);
        unsigned c1 = (vb == m1) ? (unsigned)bi : 0xffffffffu;
        unsigned i1 = __reduce_min_sync(0xffffffffu, c1);
        if (lane == 0) { bufv[par][w] = m1; bufi[par][w] = i1; }
        __syncthreads();
        unsigned v2 = bufv[par][lane];
        unsigned i2 = bufi[par][lane];
        unsigned m2 = __reduce_max_sync(0xffffffffu, v2);
        unsigned c2 = (v2 == m2) ? i2 : 0xffffffffu;
        far = (int)__reduce_min_sync(0xffffffffu, c2);
        if (t == 0) g_cent[b * SS + it] = far;
        par ^= 1;
    }
}

// ---------------- Ball query + fused layer0 GEMM (9->64) ----------------
__global__ __launch_bounds__(256) void bqg0_kernel(const float* __restrict__ xyz,
                                                   const float* __restrict__ points,
                                                   float* __restrict__ out_newxyz,
                                                   const float* __restrict__ W0,
                                                   const float* __restrict__ b0)
{
    __shared__ float4 sp[2048];
    __shared__ float sW[64 * 9];
    __shared__ float sB[64];
    __shared__ float swp[8][64];
    __shared__ float swq[8][64];

    int b    = blockIdx.x >> 7;                       // 128 blocks per batch
    int warp = threadIdx.x >> 5;
    int lane = threadIdx.x & 31;
    int t    = threadIdx.x;
    int s    = ((blockIdx.x & 127) << 3) + warp;      // centroid within batch

    // stage layer0 weights (ordered by first tile-loop barrier)
    for (int i = t; i < 576; i += 256) sW[i] = W0[i];
    if (t < 64) sB[t] = b0[t];

    int cidx = g_cent[b * SS + s];
    const float* cp = xyz + ((size_t)b * NN + cidx) * 3;
    float cx = cp[0], cy = cp[1], cz = cp[2];
    float cn2 = fmaf(cz, cz, fmaf(cy, cy, __fmul_rn(cx, cx)));
    if (lane < 3) out_newxyz[(b * SS + s) * 3 + lane] = cp[lane];

    const float R2 = 0.04f;   // float32 of radius**2
    float dl = 3.4e38f;       // rank-`lane` distance (sentinel = empty)
    int   il = 0;

    for (int tile = 0; tile < 4; ++tile) {
        __syncthreads();
        for (int i = t; i < 2048; i += 256) {
            int gp = tile * 2048 + i;
            const float* pp = xyz + ((size_t)b * NN + gp) * 3;
            float px = pp[0], py = pp[1], pz = pp[2];
            sp[i] = make_float4(px, py, pz, fmaf(pz, pz, fmaf(py, py, __fmul_rn(px, px))));
        }
        __syncthreads();
        for (int chunk = 0; chunk < 64; ++chunk) {
            float4 p = sp[chunk * 32 + lane];
            float dot = fmaf(cz, p.z, fmaf(cy, p.y, __fmul_rn(cx, p.x)));
            float d   = __fsub_rn(__fadd_rn(cn2, p.w), __fmul_rn(2.0f, dot));
            float d31 = __shfl_sync(0xffffffffu, dl, 31);
            unsigned mask = __ballot_sync(0xffffffffu, d <= R2 && d < d31);
            while (mask) {
                int c0 = __ffs(mask) - 1;             // ascending lane = ascending index
                mask &= mask - 1;
                float dc = __shfl_sync(0xffffffffu, d, c0);
                d31 = __shfl_sync(0xffffffffu, dl, 31);
                if (dc < d31) {                       // strict <: later equal never displaces
                    int pos = __popc(__ballot_sync(0xffffffffu, dl <= dc)); // after equals -> stable
                    float dprev = __shfl_up_sync(0xffffffffu, dl, 1);
                    int   iprev = __shfl_up_sync(0xffffffffu, il, 1);
                    int ic = tile * 2048 + chunk * 32 + c0;
                    if (lane >= pos) {
                        dl = (lane == pos) ? dc : dprev;
                        il = (lane == pos) ? ic : iprev;
                    }
                }
            }
        }
    }

    // radius replacement + gather of the 9 input channels (thread = one column)
    int first = __shfl_sync(0xffffffffu, il, 0);
    int gi = (dl > R2) ? first : il;
    const float* pr = points + ((size_t)b * NN + gi) * DD;
    float x[DD];
#pragma unroll
    for (int c = 0; c < DD; c++) x[c] = pr[c];

    // fused 9->64 layer: thread computes its column for all 64 channels
    size_t col = (size_t)(b * SS + ((blockIdx.x & 127) << 3)) * KK + t;
#pragma unroll 8
    for (int r = 0; r < 64; ++r) {
        float acc = 0.0f;
#pragma unroll
        for (int k = 0; k < DD; k++) acc = fmaf(sW[r * DD + k], x[k], acc);
        float y = acc + sB[r];
        g_Y0[(size_t)r * MCOL + col] = y;      // coalesced 1KB row-store per block
        float ps = y, pq = y * y;
#pragma unroll
        for (int o = 16; o > 0; o >>= 1) {
            ps += __shfl_xor_sync(0xffffffffu, ps, o);
            pq += __shfl_xor_sync(0xffffffffu, pq, o);
        }
        if (lane == 0) { swp[warp][r] = ps; swq[warp][r] = pq; }
    }
    __syncthreads();
    if (t < 64) {
        double a = 0.0, q = 0.0;
#pragma unroll
        for (int wv = 0; wv < 8; wv++) { a += (double)swp[wv][t]; q += (double)swq[wv][t]; }
        g_ps [(size_t)t * NBLKMAX + blockIdx.x] = a;
        g_pss[(size_t)t * NBLKMAX + blockIdx.x] = q;
    }
}

// ---------------- GEMM layers 1/2 (FFMA2); POOL fuses maxpool ----------------
// 256 threads, tile = COUT rows x 128 cols. thread = R rows x 8 cols (4 f32x2 accs/row).
// BN stats: per-thread (ps,pq) written to Xs-aliased scratch (Xs dead after k-loop),
// reduced by t<COUT with a fixed ascending 16-term sum (deterministic).
template<int CIN, int COUT, int LAYER, bool POOL>
__global__ __launch_bounds__(256) void gemm_kernel(const float* __restrict__ X,
                                                   float* __restrict__ Y,
                                                   const float* __restrict__ W,
                                                   const float* __restrict__ Bv)
{
    constexpr int R = COUT / 16;
    extern __shared__ float sm[];
    float* WsT  = sm;                    // [CIN][COUT] transposed weights
    float* Xs   = WsT + CIN * COUT;      // [CIN][128]  (aliased as stats scratch later)

    int t = threadIdx.x;
    size_t col0 = (size_t)blockIdx.x * 128;

    for (int i = t; i < CIN * COUT; i += 256) {
        int k = i / COUT, r = i - k * COUT;
        WsT[i] = W[r * CIN + k];
    }
    for (int i = t; i < CIN * 128; i += 256) {
        int c = i >> 7, x = i & 127;
        float v = X[(size_t)c * MCOL + col0 + x];
        v = fmaxf(fmaf(g_scl[LAYER - 1][c], v, g_shf[LAYER - 1][c]), 0.0f);
        Xs[i] = v;
    }
    __syncthreads();

    int cg = t & 15, rg = t >> 4;
    unsigned long long acc[R][4];
#pragma unroll
    for (int r = 0; r < R; r++)
#pragma unroll
        for (int c = 0; c < 4; c++) acc[r][c] = 0ull;

    const ulonglong2* Xs2 = reinterpret_cast<const ulonglong2*>(Xs);
#pragma unroll
    for (int k = 0; k < CIN; k++) {
        ulonglong2 xa = Xs2[k * 32 + cg * 2];
        ulonglong2 xb = Xs2[k * 32 + cg * 2 + 1];
        unsigned long long xs4[4] = {xa.x, xa.y, xb.x, xb.y};
        const float4* Wr = reinterpret_cast<const float4*>(WsT + k * COUT + rg * R);
#pragma unroll
        for (int rr4 = 0; rr4 < R; rr4 += 4) {
            float4 wv = Wr[rr4 / 4];
            float wa[4] = {wv.x, wv.y, wv.z, wv.w};
#pragma unroll
            for (int q = 0; q < 4; q++) {
                unsigned long long w2 = pack2(wa[q], wa[q]);
#pragma unroll
                for (int c = 0; c < 4; c++)
                    acc[rr4 + q][c] = fma2(w2, xs4[c], acc[rr4 + q][c]);
            }
        }
    }

    __syncthreads();                      // Xs reads complete -> reuse as stats scratch
    float* sps = Xs;                      // [COUT][17] padded
    float* spq = Xs + COUT * 17;

#pragma unroll
    for (int rr = 0; rr < R; rr++) {
        int r = rg * R + rr;
        float bb = Bv[r];
        float y[8];
#pragma unroll
        for (int c = 0; c < 4; c++) {
            float a, b2;
            unpack2(acc[rr][c], a, b2);
            y[2 * c]     = a + bb;
            y[2 * c + 1] = b2 + bb;
        }
        if (!POOL) {
            *reinterpret_cast<float4*>(Y + (size_t)r * MCOL + col0 + cg * 8) =
                make_float4(y[0], y[1], y[2], y[3]);
            *reinterpret_cast<float4*>(Y + (size_t)r * MCOL + col0 + cg * 8 + 4) =
                make_float4(y[4], y[5], y[6], y[7]);
        } else {
            // raw-y max over this thread's 8 cols, then over the 4 cg-threads of the
            // 32-col group (affine with scale>0 and relu commute with max exactly)
            float pm = y[0];
#pragma unroll
            for (int c = 1; c < 8; c++) pm = fmaxf(pm, y[c]);
            pm = fmaxf(pm, __shfl_xor_sync(0xffffffffu, pm, 1));
            pm = fmaxf(pm, __shfl_xor_sync(0xffffffffu, pm, 2));
            if ((cg & 3) == 0)
                g_P2[((size_t)blockIdx.x * 4 + (cg >> 2)) * 128 + r] = pm;
        }
        float ps = ((y[0] + y[1]) + (y[2] + y[3])) + ((y[4] + y[5]) + (y[6] + y[7]));
        float pq = ((y[0]*y[0] + y[1]*y[1]) + (y[2]*y[2] + y[3]*y[3]))
                 + ((y[4]*y[4] + y[5]*y[5]) + (y[6]*y[6] + y[7]*y[7]));
        sps[r * 17 + cg] = ps;
        spq[r * 17 + cg] = pq;
    }
    __syncthreads();
    if (t < COUT) {
        float a0 = 0.0f, q0 = 0.0f;
        double a = 0.0, q = 0.0;
#pragma unroll
        for (int i = 0; i < 16; i++) { a += (double)sps[t * 17 + i]; q += (double)spq[t * 17 + i]; }
        (void)a0; (void)q0;
        g_ps [(size_t)t * NBLKMAX + blockIdx.x] = a;
        g_pss[(size_t)t * NBLKMAX + blockIdx.x] = q;
    }
}

// ---------------- BN finalize: one block per channel, 512-thread deterministic sum ------
__global__ __launch_bounds__(512) void finalize_kernel(const float* __restrict__ gamma,
                                                       const float* __restrict__ beta,
                                                       int layer, int nblk)
{
    int c = blockIdx.x, t = threadIdx.x;
    __shared__ double sh1[512], sh2[512];
    double a = 0.0, q = 0.0;
    for (int i = t; i < nblk; i += 512) {
        a += g_ps [(size_t)c * NBLKMAX + i];
        q += g_pss[(size_t)c * NBLKMAX + i];
    }
    sh1[t] = a; sh2[t] = q;
    __syncthreads();
    for (int o = 256; o > 0; o >>= 1) {
        if (t < o) { sh1[t] += sh1[t + o]; sh2[t] += sh2[t + o]; }
        __syncthreads();
    }
    if (t == 0) {
        double n = (double)MCOL;
        double mean = sh1[0] / n;
        double var  = sh2[0] / n - mean * mean;
        float sc = gamma[c] * rsqrtf((float)var + 1e-5f);
        g_scl[layer][c] = sc;
        g_shf[layer][c] = beta[c] - (float)mean * sc;
    }
}

// ---------------- final: BN2 affine + relu on pooled values (already [ms][c]) ----------------
__global__ __launch_bounds__(256) void final_kernel(float* __restrict__ out)
{
    int g = blockIdx.x * 256 + threadIdx.x;
    int c = g & 127;
    out[g] = fmaxf(fmaf(g_scl[2][c], g_P2[g], g_shf[2][c]), 0.0f);
}

// ---------------- launch ----------------
extern "C" void kernel_launch(void* const* d_in, const int* in_sizes, int n_in,
                              void* d_out, int out_size)
{
    const float* xyz    = (const float*)d_in[0];
    const float* points = (const float*)d_in[1];
    const float* W0 = (const float*)d_in[2];
    const float* b0 = (const float*)d_in[3];
    const float* g0 = (const float*)d_in[4];
    const float* be0 = (const float*)d_in[5];
    const float* W1 = (const float*)d_in[6];
    const float* b1 = (const float*)d_in[7];
    const float* g1 = (const float*)d_in[8];
    const float* be1 = (const float*)d_in[9];
    const float* W2 = (const float*)d_in[10];
    const float* b2 = (const float*)d_in[11];
    const float* g2 = (const float*)d_in[12];
    const float* be2 = (const float*)d_in[13];

    float* out      = (float*)d_out;
    float* out_feat = out + BB * SS * 3;

    float *pY0, *pY1;
    cudaGetSymbolAddress((void**)&pY0, g_Y0);
    cudaGetSymbolAddress((void**)&pY1, g_Y1);

    // 0 pads: ncu capture slot (#4) = gemm1

    // FPS (96KB dynamic smem)
    cudaFuncSetAttribute(fps_kernel, cudaFuncAttributeMaxDynamicSharedMemorySize, 3 * NN * 4);
    fps_kernel<<<BB, 1024, 3 * NN * 4>>>(xyz);

    // ball query + fused layer0 (9->64) + new_xyz output
    bqg0_kernel<<<NBLK0, 256>>>(xyz, points, out, W0, b0);
    finalize_kernel<<<64, 512>>>(g0, be0, 0, NBLK0);

    // layer 1: 64 -> 64 (applies BN0+relu on input)
    {
        size_t smem = (size_t)(64 * 64 + 64 * 128) * 4;
        cudaFuncSetAttribute(gemm_kernel<64, 64, 1, false>, cudaFuncAttributeMaxDynamicSharedMemorySize, (int)smem);
        gemm_kernel<64, 64, 1, false><<<NBLK1, 256, smem>>>(pY0, pY1, W1, b1);
        finalize_kernel<<<64, 512>>>(g1, be1, 1, NBLK1);
    }
    // layer 2: 64 -> 128, maxpool fused (no Y2 materialization)
    {
        size_t smem = (size_t)(64 * 128 + 64 * 128) * 4;
        cudaFuncSetAttribute(gemm_kernel<64, 128, 2, true>, cudaFuncAttributeMaxDynamicSharedMemorySize, (int)smem);
        gemm_kernel<64, 128, 2, true><<<NBLK1, 256, smem>>>(pY1, pY0 /*unused*/, W2, b2);
        finalize_kernel<<<128, 512>>>(g2, be2, 2, NBLK1);
    }
    // BN2 affine + relu on pooled values -> feature output
    final_kernel<<<(BB * SS * 128) / 256, 256>>>(out_feat);
}

// round 10
// speedup vs baseline: 1.5595x; 1.5595x over previous
#include <cuda_runtime.h>
#include <cstddef>

#define BB   16
#define NN   8192
#define SS   1024        // NPOINT
#define KK   32          // NSAMPLE
#define DD   9
#define NPT  (BB*NN)     // 131072 unique columns
#define MCOLD ((double)(BB*SS*KK))   // BN divisor = gathered count 524288
#define NBLKMAX 4096

// ---------------- device scratch (static) ----------------
__device__ float  g_Y0[(size_t)64  * NPT];
__device__ float  g_Y1[(size_t)64  * NPT];
__device__ float  g_Y2T[(size_t)NPT * 128];   // column-major layer2 out
__device__ int    g_cent[BB * SS];
__device__ int    g_idx[BB * SS * KK];        // gathered column ids
__device__ int    g_cnt[NPT];                 // gather multiplicity
__device__ double g_ps [(size_t)128 * NBLKMAX];
__device__ double g_pss[(size_t)128 * NBLKMAX];
__device__ float  g_scl[3][128];
__device__ float  g_shf[3][128];

// ---------------- f32x2 packed helpers (sm_100+) ----------------
__device__ __forceinline__ unsigned long long pack2(float a, float b) {
    unsigned long long r;
    asm("mov.b64 %0, {%1, %2};" : "=l"(r) : "f"(a), "f"(b));
    return r;
}
__device__ __forceinline__ void unpack2(unsigned long long v, float& a, float& b) {
    asm("mov.b64 {%0, %1}, %2;" : "=f"(a), "=f"(b) : "l"(v));
}
__device__ __forceinline__ unsigned long long add2(unsigned long long a, unsigned long long b) {
    unsigned long long r;
    asm("add.rn.f32x2 %0, %1, %2;" : "=l"(r) : "l"(a), "l"(b));
    return r;
}
__device__ __forceinline__ unsigned long long mul2(unsigned long long a, unsigned long long b) {
    unsigned long long r;
    asm("mul.rn.f32x2 %0, %1, %2;" : "=l"(r) : "l"(a), "l"(b));
    return r;
}
__device__ __forceinline__ unsigned long long fma2(unsigned long long a, unsigned long long b, unsigned long long c) {
    unsigned long long r;
    asm("fma.rn.f32x2 %0, %1, %2, %3;" : "=l"(r) : "l"(a), "l"(b), "l"(c));
    return r;
}

// ---------------- reset counts ----------------
__global__ void reset_kernel() {
    g_cnt[blockIdx.x * 256 + threadIdx.x] = 0;
}

// ---------------- FPS (R5/R8-exact) ----------------
__global__ __launch_bounds__(1024) void fps_kernel(const float* __restrict__ xyz)
{
    extern __shared__ float sh[];
    float* sx = sh;
    float* sy = sh + NN;
    float* sz = sh + 2 * NN;
    __shared__ unsigned bufv[2][32];
    __shared__ unsigned bufi[2][32];

    int b = blockIdx.x, t = threadIdx.x;
    int lane = t & 31, w = t >> 5;
    const float* xb = xyz + (size_t)b * NN * 3;

    float xs[8], ys[8], zs[8], Dst[8];
#pragma unroll
    for (int j = 0; j < 8; j++) {
        int p = j * 1024 + t;
        xs[j] = xb[p * 3 + 0];
        ys[j] = xb[p * 3 + 1];
        zs[j] = xb[p * 3 + 2];
        Dst[j] = 1e10f;
        sx[p] = xs[j]; sy[p] = ys[j]; sz[p] = zs[j];
    }
    unsigned long long X2[4], Y2[4], Z2[4];
#pragma unroll
    for (int jp = 0; jp < 4; jp++) {
        X2[jp] = pack2(xs[2 * jp], xs[2 * jp + 1]);
        Y2[jp] = pack2(ys[2 * jp], ys[2 * jp + 1]);
        Z2[jp] = pack2(zs[2 * jp], zs[2 * jp + 1]);
    }
    if (t == 0) g_cent[b * SS] = 0;
    int far = 0, par = 0;
    __syncthreads();

    for (int it = 1; it < SS; ++it) {
        float cx = sx[far], cy = sy[far], cz = sz[far];
        unsigned long long cx2 = pack2(-cx, -cx);
        unsigned long long cy2 = pack2(-cy, -cy);
        unsigned long long cz2 = pack2(-cz, -cz);
        float bv = -1.0f; int bi = 0;
#pragma unroll
        for (int jp = 0; jp < 4; jp++) {
            unsigned long long dx2 = add2(X2[jp], cx2);
            unsigned long long dy2 = add2(Y2[jp], cy2);
            unsigned long long dz2 = add2(Z2[jp], cz2);
            unsigned long long d2 = fma2(dz2, dz2, fma2(dy2, dy2, mul2(dx2, dx2)));
            float dlo, dhi;
            unpack2(d2, dlo, dhi);
            float nlo = fminf(Dst[2 * jp], dlo);
            float nhi = fminf(Dst[2 * jp + 1], dhi);
            Dst[2 * jp] = nlo;
            Dst[2 * jp + 1] = nhi;
            if (nlo > bv) { bv = nlo; bi = 2 * jp * 1024 + t; }
            if (nhi > bv) { bv = nhi; bi = (2 * jp + 1) * 1024 + t; }
        }
        unsigned vb = __float_as_uint(bv);
        unsigned m1 = __reduce_max_sync(0xffffffffu, vb);
        unsigned c1 = (vb == m1) ? (unsigned)bi : 0xffffffffu;
        unsigned i1 = __reduce_min_sync(0xffffffffu, c1);
        if (lane == 0) { bufv[par][w] = m1; bufi[par][w] = i1; }
        __syncthreads();
        unsigned v2 = bufv[par][lane];
        unsigned i2 = bufi[par][lane];
        unsigned m2 = __reduce_max_sync(0xffffffffu, v2);
        unsigned c2 = (v2 == m2) ? i2 : 0xffffffffu;
        far = (int)__reduce_min_sync(0xffffffffu, c2);
        if (t == 0) g_cent[b * SS + it] = far;
        par ^= 1;
    }
}

// ---------------- Ball query: top-32 + idx store + count histogram ----------------
__global__ __launch_bounds__(256) void bq_kernel(const float* __restrict__ xyz,
                                                 float* __restrict__ out_newxyz)
{
    __shared__ float4 sp[2048];
    int b    = blockIdx.x >> 7;
    int warp = threadIdx.x >> 5;
    int lane = threadIdx.x & 31;
    int t    = threadIdx.x;
    int s    = ((blockIdx.x & 127) << 3) + warp;

    int cidx = g_cent[b * SS + s];
    const float* cp = xyz + ((size_t)b * NN + cidx) * 3;
    float cx = cp[0], cy = cp[1], cz = cp[2];
    float cn2 = fmaf(cz, cz, fmaf(cy, cy, __fmul_rn(cx, cx)));
    if (lane < 3) out_newxyz[(b * SS + s) * 3 + lane] = cp[lane];

    const float R2 = 0.04f;
    float dl = 3.4e38f;
    int   il = 0;

    for (int tile = 0; tile < 4; ++tile) {
        __syncthreads();
        for (int i = t; i < 2048; i += 256) {
            int gp = tile * 2048 + i;
            const float* pp = xyz + ((size_t)b * NN + gp) * 3;
            float px = pp[0], py = pp[1], pz = pp[2];
            sp[i] = make_float4(px, py, pz, fmaf(pz, pz, fmaf(py, py, __fmul_rn(px, px))));
        }
        __syncthreads();
        for (int chunk = 0; chunk < 64; ++chunk) {
            float4 p = sp[chunk * 32 + lane];
            float dot = fmaf(cz, p.z, fmaf(cy, p.y, __fmul_rn(cx, p.x)));
            float d   = __fsub_rn(__fadd_rn(cn2, p.w), __fmul_rn(2.0f, dot));
            float d31 = __shfl_sync(0xffffffffu, dl, 31);
            unsigned mask = __ballot_sync(0xffffffffu, d <= R2 && d < d31);
            while (mask) {
                int c0 = __ffs(mask) - 1;
                mask &= mask - 1;
                float dc = __shfl_sync(0xffffffffu, d, c0);
                d31 = __shfl_sync(0xffffffffu, dl, 31);
                if (dc < d31) {
                    int pos = __popc(__ballot_sync(0xffffffffu, dl <= dc));
                    float dprev = __shfl_up_sync(0xffffffffu, dl, 1);
                    int   iprev = __shfl_up_sync(0xffffffffu, il, 1);
                    int ic = tile * 2048 + chunk * 32 + c0;
                    if (lane >= pos) {
                        dl = (lane == pos) ? dc : dprev;
                        il = (lane == pos) ? ic : iprev;
                    }
                }
            }
        }
    }

    int first = __shfl_sync(0xffffffffu, il, 0);
    int gi = (dl > R2) ? first : il;
    int col = b * NN + gi;
    g_idx[(b * SS + s) * KK + lane] = col;     // coalesced
    atomicAdd(&g_cnt[col], 1);                 // integer -> deterministic
}

// ---------------- layer0 on unique points: thread-per-column 9->64 ----------------
__global__ __launch_bounds__(256) void gemm0_kernel(const float* __restrict__ points,
                                                    const float* __restrict__ W0,
                                                    const float* __restrict__ b0)
{
    __shared__ float sW[576];
    __shared__ float sB[64];
    __shared__ float swp[8][64];
    __shared__ float swq[8][64];

    int t = threadIdx.x;
    int col = blockIdx.x * 256 + t;
    int warp = t >> 5, lane = t & 31;

    for (int i = t; i < 576; i += 256) sW[i] = W0[i];
    if (t < 64) sB[t] = b0[t];
    __syncthreads();

    float x[DD];
#pragma unroll
    for (int k = 0; k < DD; k++) x[k] = points[(size_t)col * DD + k];
    float cntf = (float)g_cnt[col];

#pragma unroll 8
    for (int r = 0; r < 64; ++r) {
        float acc = 0.0f;
#pragma unroll
        for (int k = 0; k < DD; k++) acc = fmaf(sW[r * DD + k], x[k], acc);
        float y = acc + sB[r];
        g_Y0[(size_t)r * NPT + col] = y;
        float ps = cntf * y, pq = cntf * (y * y);
#pragma unroll
        for (int o = 16; o > 0; o >>= 1) {
            ps += __shfl_xor_sync(0xffffffffu, ps, o);
            pq += __shfl_xor_sync(0xffffffffu, pq, o);
        }
        if (lane == 0) { swp[warp][r] = ps; swq[warp][r] = pq; }
    }
    __syncthreads();
    if (t < 64) {
        double a = 0.0, q = 0.0;
#pragma unroll
        for (int wv = 0; wv < 8; wv++) { a += (double)swp[wv][t]; q += (double)swq[wv][t]; }
        g_ps [(size_t)t * NBLKMAX + blockIdx.x] = a;
        g_pss[(size_t)t * NBLKMAX + blockIdx.x] = q;
    }
}

// ---------------- GEMM layers 1/2 (R8-exact k-loop); weighted stats; TRANS store ------
template<int COUT, int LAYER, bool TRANS>
__global__ __launch_bounds__(256) void gemm_kernel(const float* __restrict__ X,
                                                   float* __restrict__ Y,
                                                   const float* __restrict__ W,
                                                   const float* __restrict__ Bv)
{
    constexpr int CIN = 64;
    constexpr int R = COUT / 16;
    extern __shared__ float sm[];
    float* WsT  = sm;                    // [CIN][COUT]
    float* Xs   = WsT + CIN * COUT;      // [CIN][128]
    float* ssum = Xs  + CIN * 128;       // [COUT]
    float* sss  = ssum + COUT;           // [COUT]
    float* scnt = sss  + COUT;           // [128]

    int t = threadIdx.x;
    size_t col0 = (size_t)blockIdx.x * 128;

    for (int i = t; i < CIN * COUT; i += 256) {
        int k = i / COUT, r = i - k * COUT;
        WsT[i] = W[r * CIN + k];
    }
    for (int i = t; i < CIN * 128; i += 256) {
        int c = i >> 7, x = i & 127;
        float v = X[(size_t)c * NPT + col0 + x];
        v = fmaxf(fmaf(g_scl[LAYER - 1][c], v, g_shf[LAYER - 1][c]), 0.0f);
        Xs[i] = v;
    }
    if (t < 128) scnt[t] = (float)g_cnt[col0 + t];
    __syncthreads();

    int cg = t & 15, rg = t >> 4;
    unsigned long long acc[R][4];
#pragma unroll
    for (int r = 0; r < R; r++)
#pragma unroll
        for (int c = 0; c < 4; c++) acc[r][c] = 0ull;

    const ulonglong2* Xs2 = reinterpret_cast<const ulonglong2*>(Xs);
#pragma unroll
    for (int k = 0; k < CIN; k++) {
        ulonglong2 xa = Xs2[k * 32 + cg * 2];
        ulonglong2 xb = Xs2[k * 32 + cg * 2 + 1];
        unsigned long long xs4[4] = {xa.x, xa.y, xb.x, xb.y};
        const float4* Wr = reinterpret_cast<const float4*>(WsT + k * COUT + rg * R);
#pragma unroll
        for (int rr4 = 0; rr4 < R; rr4 += 4) {
            float4 wv = Wr[rr4 / 4];
            float wa[4] = {wv.x, wv.y, wv.z, wv.w};
#pragma unroll
            for (int q = 0; q < 4; q++) {
                unsigned long long w2 = pack2(wa[q], wa[q]);
#pragma unroll
                for (int c = 0; c < 4; c++)
                    acc[rr4 + q][c] = fma2(w2, xs4[c], acc[rr4 + q][c]);
            }
        }
    }

    int lane = t & 31;
    float cntc[8];
#pragma unroll
    for (int c = 0; c < 8; c++) cntc[c] = scnt[cg * 8 + c];
    float bb[R];
#pragma unroll
    for (int rr = 0; rr < R; rr++) bb[rr] = Bv[rg * R + rr];

#pragma unroll
    for (int rr = 0; rr < R; rr++) {
        int r = rg * R + rr;
        float y[8];
#pragma unroll
        for (int c = 0; c < 4; c++) {
            float a, b2;
            unpack2(acc[rr][c], a, b2);
            y[2 * c]     = a + bb[rr];
            y[2 * c + 1] = b2 + bb[rr];
        }
        if (!TRANS) {
            *reinterpret_cast<float4*>(Y + (size_t)r * NPT + col0 + cg * 8) =
                make_float4(y[0], y[1], y[2], y[3]);
            *reinterpret_cast<float4*>(Y + (size_t)r * NPT + col0 + cg * 8 + 4) =
                make_float4(y[4], y[5], y[6], y[7]);
        }
        float ps = 0.0f, pq = 0.0f;
#pragma unroll
        for (int c = 0; c < 8; c++) {
            ps = fmaf(cntc[c], y[c], ps);
            pq = fmaf(cntc[c], y[c] * y[c], pq);
        }
#pragma unroll
        for (int o = 8; o > 0; o >>= 1) {
            ps += __shfl_xor_sync(0xffffffffu, ps, o);
            pq += __shfl_xor_sync(0xffffffffu, pq, o);
        }
        if ((lane & 15) == 0) { ssum[r] = ps; sss[r] = pq; }
    }
    if (TRANS) {
        // column-major store: per col, this thread's 8 consecutive rows -> 2 x float4
#pragma unroll
        for (int c = 0; c < 8; c++) {
            float yv[8];
#pragma unroll
            for (int rr = 0; rr < R; rr++) {
                float a, b2;
                unpack2(acc[rr][c >> 1], a, b2);
                yv[rr] = ((c & 1) ? b2 : a) + bb[rr];
            }
            size_t base = (col0 + cg * 8 + c) * 128 + rg * R;
            *reinterpret_cast<float4*>(Y + base)     = make_float4(yv[0], yv[1], yv[2], yv[3]);
            *reinterpret_cast<float4*>(Y + base + 4) = make_float4(yv[4], yv[5], yv[6], yv[7]);
        }
    }
    __syncthreads();
    if (t < COUT) {
        g_ps [(size_t)t * NBLKMAX + blockIdx.x] = (double)ssum[t];
        g_pss[(size_t)t * NBLKMAX + blockIdx.x] = (double)sss[t];
    }
}

// ---------------- BN finalize (R8-style, 128 threads) ----------------
__global__ __launch_bounds__(128) void finalize_kernel(const float* __restrict__ gamma,
                                                       const float* __restrict__ beta,
                                                       int layer, int nblk)
{
    int c = blockIdx.x, t = threadIdx.x;
    __shared__ double sh1[128], sh2[128];
    double a = 0.0, q = 0.0;
    for (int i = t; i < nblk; i += 128) {
        a += g_ps [(size_t)c * NBLKMAX + i];
        q += g_pss[(size_t)c * NBLKMAX + i];
    }
    sh1[t] = a; sh2[t] = q;
    __syncthreads();
    for (int o = 64; o > 0; o >>= 1) {
        if (t < o) { sh1[t] += sh1[t + o]; sh2[t] += sh2[t + o]; }
        __syncthreads();
    }
    if (t == 0) {
        double mean = sh1[0] / MCOLD;
        double var  = sh2[0] / MCOLD - mean * mean;
        float sc = gamma[c] * rsqrtf((float)var + 1e-5f);
        g_scl[layer][c] = sc;
        g_shf[layer][c] = beta[c] - (float)mean * sc;
    }
}

// ---------------- final: gather-max over 32 idx cols + BN2 affine + relu ------------
__global__ __launch_bounds__(256) void final_kernel(float* __restrict__ out)
{
    int warp = threadIdx.x >> 5, lane = threadIdx.x & 31;
    int cent = blockIdx.x * 8 + warp;
    int myidx = g_idx[cent * KK + lane];       // coalesced 128B
    float4 mx = make_float4(-3.4e38f, -3.4e38f, -3.4e38f, -3.4e38f);
#pragma unroll
    for (int j = 0; j < KK; j++) {
        int col = __shfl_sync(0xffffffffu, myidx, j);
        float4 v = *reinterpret_cast<const float4*>(g_Y2T + (size_t)col * 128 + lane * 4);
        mx.x = fmaxf(mx.x, v.x);
        mx.y = fmaxf(mx.y, v.y);
        mx.z = fmaxf(mx.z, v.z);
        mx.w = fmaxf(mx.w, v.w);
    }
    int c0 = lane * 4;
    float4 o;
    o.x = fmaxf(fmaf(g_scl[2][c0 + 0], mx.x, g_shf[2][c0 + 0]), 0.0f);
    o.y = fmaxf(fmaf(g_scl[2][c0 + 1], mx.y, g_shf[2][c0 + 1]), 0.0f);
    o.z = fmaxf(fmaf(g_scl[2][c0 + 2], mx.z, g_shf[2][c0 + 2]), 0.0f);
    o.w = fmaxf(fmaf(g_scl[2][c0 + 3], mx.w, g_shf[2][c0 + 3]), 0.0f);
    *reinterpret_cast<float4*>(out + (size_t)cent * 128 + c0) = o;
}

// ---------------- launch ----------------
extern "C" void kernel_launch(void* const* d_in, const int* in_sizes, int n_in,
                              void* d_out, int out_size)
{
    const float* xyz    = (const float*)d_in[0];
    const float* points = (const float*)d_in[1];
    const float* W0 = (const float*)d_in[2];
    const float* b0 = (const float*)d_in[3];
    const float* g0 = (const float*)d_in[4];
    const float* be0 = (const float*)d_in[5];
    const float* W1 = (const float*)d_in[6];
    const float* b1 = (const float*)d_in[7];
    const float* g1 = (const float*)d_in[8];
    const float* be1 = (const float*)d_in[9];
    const float* W2 = (const float*)d_in[10];
    const float* b2 = (const float*)d_in[11];
    const float* g2 = (const float*)d_in[12];
    const float* be2 = (const float*)d_in[13];

    float* out      = (float*)d_out;
    float* out_feat = out + BB * SS * 3;

    float *pY0, *pY1, *pY2T;
    cudaGetSymbolAddress((void**)&pY0, g_Y0);
    cudaGetSymbolAddress((void**)&pY1, g_Y1);
    cudaGetSymbolAddress((void**)&pY2T, g_Y2T);

    // counts reset (fresh every graph replay)
    reset_kernel<<<NPT / 256, 256>>>();

    // FPS (96KB dynamic smem)
    cudaFuncSetAttribute(fps_kernel, cudaFuncAttributeMaxDynamicSharedMemorySize, 3 * NN * 4);
    fps_kernel<<<BB, 1024, 3 * NN * 4>>>(xyz);

    // ball query: idx + histogram + new_xyz
    bq_kernel<<<BB * 128, 256>>>(xyz, out);

    // layer 0 on unique points (capture slot #4)
    gemm0_kernel<<<NPT / 256, 256>>>(points, W0, b0);
    finalize_kernel<<<64, 128>>>(g0, be0, 0, NPT / 256);

    // layer 1: 64 -> 64
    {
        size_t smem = (size_t)(64 * 64 + 64 * 128 + 2 * 64 + 128) * 4;
        cudaFuncSetAttribute(gemm_kernel<64, 1, false>, cudaFuncAttributeMaxDynamicSharedMemorySize, (int)smem);
        gemm_kernel<64, 1, false><<<NPT / 128, 256, smem>>>(pY0, pY1, W1, b1);
        finalize_kernel<<<64, 128>>>(g1, be1, 1, NPT / 128);
    }
    // layer 2: 64 -> 128, column-major output
    {
        size_t smem = (size_t)(64 * 128 + 64 * 128 + 2 * 128 + 128) * 4;
        cudaFuncSetAttribute(gemm_kernel<128, 2, true>, cudaFuncAttributeMaxDynamicSharedMemorySize, (int)smem);
        gemm_kernel<128, 2, true><<<NPT / 128, 256, smem>>>(pY1, pY2T, W2, b2);
        finalize_kernel<<<128, 128>>>(g2, be2, 2, NPT / 128);
    }
    // gather-max + BN2 + relu -> feature output
    final_kernel<<<(BB * SS) / 8, 256>>>(out_feat);
}

// round 11
// speedup vs baseline: 1.7947x; 1.1508x over previous
#include <cuda_runtime.h>
#include <cstddef>

#define BB   16
#define NN   8192
#define SS   1024        // NPOINT
#define KK   32          // NSAMPLE
#define DD   9
#define NPT  (BB*NN)     // 131072 unique columns
#define MCOLD ((double)(BB*SS*KK))   // BN divisor = gathered count 524288
#define NBLKMAX 4096

// ---------------- device scratch (static) ----------------
__device__ float  g_Y0[(size_t)64  * NPT];
__device__ float  g_Y1[(size_t)64  * NPT];
__device__ float  g_Y2T[(size_t)NPT * 128];   // column-major layer2 out
__device__ int    g_cent[BB * SS];
__device__ int    g_idx[BB * SS * KK];        // gathered column ids
__device__ int    g_cnt[NPT];                 // gather multiplicity
__device__ int    g_prog[BB];                 // fps progress per batch
__device__ double g_ps [(size_t)128 * NBLKMAX];
__device__ double g_pss[(size_t)128 * NBLKMAX];
__device__ float  g_scl[3][128];
__device__ float  g_shf[3][128];

// ---------------- f32x2 packed helpers (sm_100+) ----------------
__device__ __forceinline__ unsigned long long pack2(float a, float b) {
    unsigned long long r;
    asm("mov.b64 %0, {%1, %2};" : "=l"(r) : "f"(a), "f"(b));
    return r;
}
__device__ __forceinline__ void unpack2(unsigned long long v, float& a, float& b) {
    asm("mov.b64 {%0, %1}, %2;" : "=f"(a), "=f"(b) : "l"(v));
}
__device__ __forceinline__ unsigned long long add2(unsigned long long a, unsigned long long b) {
    unsigned long long r;
    asm("add.rn.f32x2 %0, %1, %2;" : "=l"(r) : "l"(a), "l"(b));
    return r;
}
__device__ __forceinline__ unsigned long long mul2(unsigned long long a, unsigned long long b) {
    unsigned long long r;
    asm("mul.rn.f32x2 %0, %1, %2;" : "=l"(r) : "l"(a), "l"(b));
    return r;
}
__device__ __forceinline__ unsigned long long fma2(unsigned long long a, unsigned long long b, unsigned long long c) {
    unsigned long long r;
    asm("fma.rn.f32x2 %0, %1, %2, %3;" : "=l"(r) : "l"(a), "l"(b), "l"(c));
    return r;
}

// ---------------- pads + reset ----------------
__global__ void pad_kernel() {}
__global__ void reset_kernel() {
    int i = blockIdx.x * 256 + threadIdx.x;
    g_cnt[i] = 0;
    if (i < BB) g_prog[i] = 0;
}

// ================= role: FPS (bids 0..15) — R10-exact + progress publish =================
__device__ __forceinline__ void fps_role(const float* __restrict__ xyz, float* sh, int b)
{
    float* sx = sh;
    float* sy = sh + NN;
    float* sz = sh + 2 * NN;
    __shared__ unsigned bufv[2][32];
    __shared__ unsigned bufi[2][32];

    int t = threadIdx.x;
    int lane = t & 31, w = t >> 5;
    const float* xb = xyz + (size_t)b * NN * 3;

    float xs[8], ys[8], zs[8], Dst[8];
#pragma unroll
    for (int j = 0; j < 8; j++) {
        int p = j * 1024 + t;
        xs[j] = xb[p * 3 + 0];
        ys[j] = xb[p * 3 + 1];
        zs[j] = xb[p * 3 + 2];
        Dst[j] = 1e10f;
        sx[p] = xs[j]; sy[p] = ys[j]; sz[p] = zs[j];
    }
    unsigned long long X2[4], Y2[4], Z2[4];
#pragma unroll
    for (int jp = 0; jp < 4; jp++) {
        X2[jp] = pack2(xs[2 * jp], xs[2 * jp + 1]);
        Y2[jp] = pack2(ys[2 * jp], ys[2 * jp + 1]);
        Z2[jp] = pack2(zs[2 * jp], zs[2 * jp + 1]);
    }
    if (t == 0) g_cent[b * SS] = 0;
    int far = 0, par = 0;
    __syncthreads();

    for (int it = 1; it < SS; ++it) {
        float cx = sx[far], cy = sy[far], cz = sz[far];
        unsigned long long cx2 = pack2(-cx, -cx);
        unsigned long long cy2 = pack2(-cy, -cy);
        unsigned long long cz2 = pack2(-cz, -cz);
        float bv = -1.0f; int bi = 0;
#pragma unroll
        for (int jp = 0; jp < 4; jp++) {
            unsigned long long dx2 = add2(X2[jp], cx2);
            unsigned long long dy2 = add2(Y2[jp], cy2);
            unsigned long long dz2 = add2(Z2[jp], cz2);
            unsigned long long d2 = fma2(dz2, dz2, fma2(dy2, dy2, mul2(dx2, dx2)));
            float dlo, dhi;
            unpack2(d2, dlo, dhi);
            float nlo = fminf(Dst[2 * jp], dlo);
            float nhi = fminf(Dst[2 * jp + 1], dhi);
            Dst[2 * jp] = nlo;
            Dst[2 * jp + 1] = nhi;
            if (nlo > bv) { bv = nlo; bi = 2 * jp * 1024 + t; }
            if (nhi > bv) { bv = nhi; bi = (2 * jp + 1) * 1024 + t; }
        }
        unsigned vb = __float_as_uint(bv);
        unsigned m1 = __reduce_max_sync(0xffffffffu, vb);
        unsigned c1 = (vb == m1) ? (unsigned)bi : 0xffffffffu;
        unsigned i1 = __reduce_min_sync(0xffffffffu, c1);
        if (lane == 0) { bufv[par][w] = m1; bufi[par][w] = i1; }
        __syncthreads();
        unsigned v2 = bufv[par][lane];
        unsigned i2 = bufi[par][lane];
        unsigned m2 = __reduce_max_sync(0xffffffffu, v2);
        unsigned c2 = (v2 == m2) ? i2 : 0xffffffffu;
        far = (int)__reduce_min_sync(0xffffffffu, c2);
        if (t == 0) {
            g_cent[b * SS + it] = far;
            if ((it & 31) == 31) { __threadfence(); atomicExch(&g_prog[b], it); }
        }
        par ^= 1;
    }
}

// ================= role: layer0 on unique points (bids 16..143, no deps) =================
__device__ __forceinline__ void g0_role(const float* __restrict__ points,
                                        const float* __restrict__ W0,
                                        const float* __restrict__ b0,
                                        float* sh, int idx)
{
    float* sW = sh;
    float* sB = sh + 576;
    int t = threadIdx.x;
    for (int i = t; i < 576; i += 1024) sW[i] = W0[i];
    if (t < 64) sB[t] = b0[t];
    __syncthreads();

    int col = idx * 1024 + t;
    float x[DD];
#pragma unroll
    for (int k = 0; k < DD; k++) x[k] = points[(size_t)col * DD + k];
#pragma unroll 8
    for (int r = 0; r < 64; ++r) {
        float acc = 0.0f;
#pragma unroll
        for (int k = 0; k < DD; k++) acc = fmaf(sW[r * DD + k], x[k], acc);
        g_Y0[(size_t)r * NPT + col] = acc + sB[r];
    }
}

// ================= role: ball query (bids 144..655) — spin on fps progress =================
__device__ __forceinline__ void bq_role(const float* __restrict__ xyz,
                                        float* __restrict__ out_newxyz,
                                        float4* sp, int idx)
{
    int g = idx >> 4, b = idx & 15;
    int t = threadIdx.x, warp = t >> 5, lane = t & 31;
    int s = (g << 5) + warp;

    if (t == 0) {
        while (atomicAdd(&g_prog[b], 0) < (g << 5) + 31) __nanosleep(256);
        __threadfence();
    }
    __syncthreads();

    int cidx = g_cent[b * SS + s];
    const float* cp = xyz + ((size_t)b * NN + cidx) * 3;
    float cx = cp[0], cy = cp[1], cz = cp[2];
    float cn2 = fmaf(cz, cz, fmaf(cy, cy, __fmul_rn(cx, cx)));
    if (lane < 3) out_newxyz[(b * SS + s) * 3 + lane] = cp[lane];

    const float R2 = 0.04f;
    float dl = 3.4e38f;
    int   il = 0;

    for (int tile = 0; tile < 4; ++tile) {
        __syncthreads();
        for (int i = t; i < 2048; i += 1024) {
            int gp = tile * 2048 + i;
            const float* pp = xyz + ((size_t)b * NN + gp) * 3;
            float px = pp[0], py = pp[1], pz = pp[2];
            sp[i] = make_float4(px, py, pz, fmaf(pz, pz, fmaf(py, py, __fmul_rn(px, px))));
        }
        __syncthreads();
        for (int chunk = 0; chunk < 64; ++chunk) {
            float4 p = sp[chunk * 32 + lane];
            float dot = fmaf(cz, p.z, fmaf(cy, p.y, __fmul_rn(cx, p.x)));
            float d   = __fsub_rn(__fadd_rn(cn2, p.w), __fmul_rn(2.0f, dot));
            float d31 = __shfl_sync(0xffffffffu, dl, 31);
            unsigned mask = __ballot_sync(0xffffffffu, d <= R2 && d < d31);
            while (mask) {
                int c0 = __ffs(mask) - 1;
                mask &= mask - 1;
                float dc = __shfl_sync(0xffffffffu, d, c0);
                d31 = __shfl_sync(0xffffffffu, dl, 31);
                if (dc < d31) {
                    int pos = __popc(__ballot_sync(0xffffffffu, dl <= dc));
                    float dprev = __shfl_up_sync(0xffffffffu, dl, 1);
                    int   iprev = __shfl_up_sync(0xffffffffu, il, 1);
                    int ic = tile * 2048 + chunk * 32 + c0;
                    if (lane >= pos) {
                        dl = (lane == pos) ? dc : dprev;
                        il = (lane == pos) ? ic : iprev;
                    }
                }
            }
        }
    }

    int first = __shfl_sync(0xffffffffu, il, 0);
    int gi = (dl > R2) ? first : il;
    int col = b * NN + gi;
    g_idx[(b * SS + s) * KK + lane] = col;
    atomicAdd(&g_cnt[col], 1);
}

// ================= fused pipeline kernel (1 block/SM by registers) =================
__global__ __launch_bounds__(1024, 1) void fused_kernel(const float* __restrict__ xyz,
                                                        const float* __restrict__ points,
                                                        float* __restrict__ out_newxyz,
                                                        const float* __restrict__ W0,
                                                        const float* __restrict__ b0)
{
    extern __shared__ float sh[];
    int bid = blockIdx.x;
    if (bid < 16)       fps_role(xyz, sh, bid);
    else if (bid < 144) g0_role(points, W0, b0, sh, bid - 16);
    else                bq_role(xyz, out_newxyz, reinterpret_cast<float4*>(sh), bid - 144);
}

// ---------------- layer0 BN stats (needs final counts; reads Y0) ----------------
__global__ __launch_bounds__(256) void stats0_kernel()
{
    __shared__ float swp[8][64];
    __shared__ float swq[8][64];
    int t = threadIdx.x;
    int col = blockIdx.x * 256 + t;
    int warp = t >> 5, lane = t & 31;
    float cntf = (float)g_cnt[col];

#pragma unroll 8
    for (int r = 0; r < 64; ++r) {
        float y = g_Y0[(size_t)r * NPT + col];
        float ps = cntf * y, pq = cntf * (y * y);
#pragma unroll
        for (int o = 16; o > 0; o >>= 1) {
            ps += __shfl_xor_sync(0xffffffffu, ps, o);
            pq += __shfl_xor_sync(0xffffffffu, pq, o);
        }
        if (lane == 0) { swp[warp][r] = ps; swq[warp][r] = pq; }
    }
    __syncthreads();
    if (t < 64) {
        double a = 0.0, q = 0.0;
#pragma unroll
        for (int wv = 0; wv < 8; wv++) { a += (double)swp[wv][t]; q += (double)swq[wv][t]; }
        g_ps [(size_t)t * NBLKMAX + blockIdx.x] = a;
        g_pss[(size_t)t * NBLKMAX + blockIdx.x] = q;
    }
}

// ---------------- GEMM layers 1/2 (R10-exact); weighted stats; TRANS store ------
template<int COUT, int LAYER, bool TRANS>
__global__ __launch_bounds__(256) void gemm_kernel(const float* __restrict__ X,
                                                   float* __restrict__ Y,
                                                   const float* __restrict__ W,
                                                   const float* __restrict__ Bv)
{
    constexpr int CIN = 64;
    constexpr int R = COUT / 16;
    extern __shared__ float sm[];
    float* WsT  = sm;                    // [CIN][COUT]
    float* Xs   = WsT + CIN * COUT;      // [CIN][128]
    float* ssum = Xs  + CIN * 128;       // [COUT]
    float* sss  = ssum + COUT;           // [COUT]
    float* scnt = sss  + COUT;           // [128]

    int t = threadIdx.x;
    size_t col0 = (size_t)blockIdx.x * 128;

    for (int i = t; i < CIN * COUT; i += 256) {
        int k = i / COUT, r = i - k * COUT;
        WsT[i] = W[r * CIN + k];
    }
    for (int i = t; i < CIN * 128; i += 256) {
        int c = i >> 7, x = i & 127;
        float v = X[(size_t)c * NPT + col0 + x];
        v = fmaxf(fmaf(g_scl[LAYER - 1][c], v, g_shf[LAYER - 1][c]), 0.0f);
        Xs[i] = v;
    }
    if (t < 128) scnt[t] = (float)g_cnt[col0 + t];
    __syncthreads();

    int cg = t & 15, rg = t >> 4;
    unsigned long long acc[R][4];
#pragma unroll
    for (int r = 0; r < R; r++)
#pragma unroll
        for (int c = 0; c < 4; c++) acc[r][c] = 0ull;

    const ulonglong2* Xs2 = reinterpret_cast<const ulonglong2*>(Xs);
#pragma unroll
    for (int k = 0; k < CIN; k++) {
        ulonglong2 xa = Xs2[k * 32 + cg * 2];
        ulonglong2 xb = Xs2[k * 32 + cg * 2 + 1];
        unsigned long long xs4[4] = {xa.x, xa.y, xb.x, xb.y};
        const float4* Wr = reinterpret_cast<const float4*>(WsT + k * COUT + rg * R);
#pragma unroll
        for (int rr4 = 0; rr4 < R; rr4 += 4) {
            float4 wv = Wr[rr4 / 4];
            float wa[4] = {wv.x, wv.y, wv.z, wv.w};
#pragma unroll
            for (int q = 0; q < 4; q++) {
                unsigned long long w2 = pack2(wa[q], wa[q]);
#pragma unroll
                for (int c = 0; c < 4; c++)
                    acc[rr4 + q][c] = fma2(w2, xs4[c], acc[rr4 + q][c]);
            }
        }
    }

    int lane = t & 31;
    float cntc[8];
#pragma unroll
    for (int c = 0; c < 8; c++) cntc[c] = scnt[cg * 8 + c];
    float bb[R];
#pragma unroll
    for (int rr = 0; rr < R; rr++) bb[rr] = Bv[rg * R + rr];

#pragma unroll
    for (int rr = 0; rr < R; rr++) {
        int r = rg * R + rr;
        float y[8];
#pragma unroll
        for (int c = 0; c < 4; c++) {
            float a, b2;
            unpack2(acc[rr][c], a, b2);
            y[2 * c]     = a + bb[rr];
            y[2 * c + 1] = b2 + bb[rr];
        }
        if (!TRANS) {
            *reinterpret_cast<float4*>(Y + (size_t)r * NPT + col0 + cg * 8) =
                make_float4(y[0], y[1], y[2], y[3]);
            *reinterpret_cast<float4*>(Y + (size_t)r * NPT + col0 + cg * 8 + 4) =
                make_float4(y[4], y[5], y[6], y[7]);
        }
        float ps = 0.0f, pq = 0.0f;
#pragma unroll
        for (int c = 0; c < 8; c++) {
            ps = fmaf(cntc[c], y[c], ps);
            pq = fmaf(cntc[c], y[c] * y[c], pq);
        }
#pragma unroll
        for (int o = 8; o > 0; o >>= 1) {
            ps += __shfl_xor_sync(0xffffffffu, ps, o);
            pq += __shfl_xor_sync(0xffffffffu, pq, o);
        }
        if ((lane & 15) == 0) { ssum[r] = ps; sss[r] = pq; }
    }
    if (TRANS) {
#pragma unroll
        for (int c = 0; c < 8; c++) {
            float yv[8];
#pragma unroll
            for (int rr = 0; rr < R; rr++) {
                float a, b2;
                unpack2(acc[rr][c >> 1], a, b2);
                yv[rr] = ((c & 1) ? b2 : a) + bb[rr];
            }
            size_t base = (col0 + cg * 8 + c) * 128 + rg * R;
            *reinterpret_cast<float4*>(Y + base)     = make_float4(yv[0], yv[1], yv[2], yv[3]);
            *reinterpret_cast<float4*>(Y + base + 4) = make_float4(yv[4], yv[5], yv[6], yv[7]);
        }
    }
    __syncthreads();
    if (t < COUT) {
        g_ps [(size_t)t * NBLKMAX + blockIdx.x] = (double)ssum[t];
        g_pss[(size_t)t * NBLKMAX + blockIdx.x] = (double)sss[t];
    }
}

// ---------------- BN finalize ----------------
__global__ __launch_bounds__(128) void finalize_kernel(const float* __restrict__ gamma,
                                                       const float* __restrict__ beta,
                                                       int layer, int nblk)
{
    int c = blockIdx.x, t = threadIdx.x;
    __shared__ double sh1[128], sh2[128];
    double a = 0.0, q = 0.0;
    for (int i = t; i < nblk; i += 128) {
        a += g_ps [(size_t)c * NBLKMAX + i];
        q += g_pss[(size_t)c * NBLKMAX + i];
    }
    sh1[t] = a; sh2[t] = q;
    __syncthreads();
    for (int o = 64; o > 0; o >>= 1) {
        if (t < o) { sh1[t] += sh1[t + o]; sh2[t] += sh2[t + o]; }
        __syncthreads();
    }
    if (t == 0) {
        double mean = sh1[0] / MCOLD;
        double var  = sh2[0] / MCOLD - mean * mean;
        float sc = gamma[c] * rsqrtf((float)var + 1e-5f);
        g_scl[layer][c] = sc;
        g_shf[layer][c] = beta[c] - (float)mean * sc;
    }
}

// ---------------- final: gather-max over 32 idx cols + BN2 affine + relu ------------
__global__ __launch_bounds__(256) void final_kernel(float* __restrict__ out)
{
    int warp = threadIdx.x >> 5, lane = threadIdx.x & 31;
    int cent = blockIdx.x * 8 + warp;
    int myidx = g_idx[cent * KK + lane];
    float4 mx = make_float4(-3.4e38f, -3.4e38f, -3.4e38f, -3.4e38f);
#pragma unroll
    for (int j = 0; j < KK; j++) {
        int col = __shfl_sync(0xffffffffu, myidx, j);
        float4 v = *reinterpret_cast<const float4*>(g_Y2T + (size_t)col * 128 + lane * 4);
        mx.x = fmaxf(mx.x, v.x);
        mx.y = fmaxf(mx.y, v.y);
        mx.z = fmaxf(mx.z, v.z);
        mx.w = fmaxf(mx.w, v.w);
    }
    int c0 = lane * 4;
    float4 o;
    o.x = fmaxf(fmaf(g_scl[2][c0 + 0], mx.x, g_shf[2][c0 + 0]), 0.0f);
    o.y = fmaxf(fmaf(g_scl[2][c0 + 1], mx.y, g_shf[2][c0 + 1]), 0.0f);
    o.z = fmaxf(fmaf(g_scl[2][c0 + 2], mx.z, g_shf[2][c0 + 2]), 0.0f);
    o.w = fmaxf(fmaf(g_scl[2][c0 + 3], mx.w, g_shf[2][c0 + 3]), 0.0f);
    *reinterpret_cast<float4*>(out + (size_t)cent * 128 + c0) = o;
}

// ---------------- launch ----------------
extern "C" void kernel_launch(void* const* d_in, const int* in_sizes, int n_in,
                              void* d_out, int out_size)
{
    const float* xyz    = (const float*)d_in[0];
    const float* points = (const float*)d_in[1];
    const float* W0 = (const float*)d_in[2];
    const float* b0 = (const float*)d_in[3];
    const float* g0 = (const float*)d_in[4];
    const float* be0 = (const float*)d_in[5];
    const float* W1 = (const float*)d_in[6];
    const float* b1 = (const float*)d_in[7];
    const float* g1 = (const float*)d_in[8];
    const float* be1 = (const float*)d_in[9];
    const float* W2 = (const float*)d_in[10];
    const float* b2 = (const float*)d_in[11];
    const float* g2 = (const float*)d_in[12];
    const float* be2 = (const float*)d_in[13];

    float* out      = (float*)d_out;
    float* out_feat = out + BB * SS * 3;

    float *pY0, *pY1, *pY2T;
    cudaGetSymbolAddress((void**)&pY0, g_Y0);
    cudaGetSymbolAddress((void**)&pY1, g_Y1);
    cudaGetSymbolAddress((void**)&pY2T, g_Y2T);

    // reset counts + progress (fresh every graph replay); 2 pads -> ncu slot #4 = fused
    reset_kernel<<<NPT / 256, 256>>>();
    pad_kernel<<<1, 32>>>();
    pad_kernel<<<1, 32>>>();

    // fused fps + gemm0(Y0) + ballquery pipeline (96KB smem, 1 block/SM via regs)
    const int FUSED_SMEM = 3 * NN * 4;
    cudaFuncSetAttribute(fused_kernel, cudaFuncAttributeMaxDynamicSharedMemorySize, FUSED_SMEM);
    fused_kernel<<<16 + 128 + 512, 1024, FUSED_SMEM>>>(xyz, points, out, W0, b0);

    // layer0 count-weighted BN stats (reads Y0), then finalize
    stats0_kernel<<<NPT / 256, 256>>>();
    finalize_kernel<<<64, 128>>>(g0, be0, 0, NPT / 256);

    // layer 1: 64 -> 64
    {
        size_t smem = (size_t)(64 * 64 + 64 * 128 + 2 * 64 + 128) * 4;
        cudaFuncSetAttribute(gemm_kernel<64, 1, false>, cudaFuncAttributeMaxDynamicSharedMemorySize, (int)smem);
        gemm_kernel<64, 1, false><<<NPT / 128, 256, smem>>>(pY0, pY1, W1, b1);
        finalize_kernel<<<64, 128>>>(g1, be1, 1, NPT / 128);
    }
    // layer 2: 64 -> 128, column-major output
    {
        size_t smem = (size_t)(64 * 128 + 64 * 128 + 2 * 128 + 128) * 4;
        cudaFuncSetAttribute(gemm_kernel<128, 2, true>, cudaFuncAttributeMaxDynamicSharedMemorySize, (int)smem);
        gemm_kernel<128, 2, true><<<NPT / 128, 256, smem>>>(pY1, pY2T, W2, b2);
        finalize_kernel<<<128, 128>>>(g2, be2, 2, NPT / 128);
    }
    // gather-max + BN2 + relu -> feature output
    final_kernel<<<(BB * SS) / 8, 256>>>(out_feat);
}

// round 12
// speedup vs baseline: 1.8093x; 1.0081x over previous
#include <cuda_runtime.h>
#include <cstddef>

#define BB   16
#define NN   8192
#define SS   1024        // NPOINT
#define KK   32          // NSAMPLE
#define DD   9
#define NPT  (BB*NN)     // 131072 unique columns
#define MCOLD ((double)(BB*SS*KK))   // BN divisor = gathered count 524288
#define NBLKMAX 4096

// ---------------- device scratch (static) ----------------
__device__ float  g_Y0[(size_t)64  * NPT];
__device__ float  g_Y1[(size_t)64  * NPT];
__device__ float  g_Y2T[(size_t)NPT * 128];   // column-major layer2 out
__device__ int    g_cent[BB * SS];
__device__ int    g_idx[BB * SS * KK];        // gathered column ids
__device__ int    g_cnt[NPT];                 // gather multiplicity
__device__ int    g_prog[BB];                 // fps progress per batch
__device__ double g_ps [(size_t)128 * NBLKMAX];
__device__ double g_pss[(size_t)128 * NBLKMAX];
__device__ float  g_scl[3][128];
__device__ float  g_shf[3][128];

// ---------------- f32x2 packed helpers (sm_100+) ----------------
__device__ __forceinline__ unsigned long long pack2(float a, float b) {
    unsigned long long r;
    asm("mov.b64 %0, {%1, %2};" : "=l"(r) : "f"(a), "f"(b));
    return r;
}
__device__ __forceinline__ void unpack2(unsigned long long v, float& a, float& b) {
    asm("mov.b64 {%0, %1}, %2;" : "=f"(a), "=f"(b) : "l"(v));
}
__device__ __forceinline__ unsigned long long add2(unsigned long long a, unsigned long long b) {
    unsigned long long r;
    asm("add.rn.f32x2 %0, %1, %2;" : "=l"(r) : "l"(a), "l"(b));
    return r;
}
__device__ __forceinline__ unsigned long long mul2(unsigned long long a, unsigned long long b) {
    unsigned long long r;
    asm("mul.rn.f32x2 %0, %1, %2;" : "=l"(r) : "l"(a), "l"(b));
    return r;
}
__device__ __forceinline__ unsigned long long fma2(unsigned long long a, unsigned long long b, unsigned long long c) {
    unsigned long long r;
    asm("fma.rn.f32x2 %0, %1, %2, %3;" : "=l"(r) : "l"(a), "l"(b), "l"(c));
    return r;
}

// ---------------- pads + reset ----------------
__global__ void pad_kernel() {}
__global__ void reset_kernel() {
    int i = blockIdx.x * 256 + threadIdx.x;
    g_cnt[i] = 0;
    if (i < BB) g_prog[i] = 0;
}

// ================= role: FPS (bids 0..15) — R10-exact + progress publish =================
__device__ __forceinline__ void fps_role(const float* __restrict__ xyz, float* sh, int b)
{
    float* sx = sh;
    float* sy = sh + NN;
    float* sz = sh + 2 * NN;
    __shared__ unsigned bufv[2][32];
    __shared__ unsigned bufi[2][32];

    int t = threadIdx.x;
    int lane = t & 31, w = t >> 5;
    const float* xb = xyz + (size_t)b * NN * 3;

    float xs[8], ys[8], zs[8], Dst[8];
#pragma unroll
    for (int j = 0; j < 8; j++) {
        int p = j * 1024 + t;
        xs[j] = xb[p * 3 + 0];
        ys[j] = xb[p * 3 + 1];
        zs[j] = xb[p * 3 + 2];
        Dst[j] = 1e10f;
        sx[p] = xs[j]; sy[p] = ys[j]; sz[p] = zs[j];
    }
    unsigned long long X2[4], Y2[4], Z2[4];
#pragma unroll
    for (int jp = 0; jp < 4; jp++) {
        X2[jp] = pack2(xs[2 * jp], xs[2 * jp + 1]);
        Y2[jp] = pack2(ys[2 * jp], ys[2 * jp + 1]);
        Z2[jp] = pack2(zs[2 * jp], zs[2 * jp + 1]);
    }
    if (t == 0) g_cent[b * SS] = 0;
    int far = 0, par = 0;
    __syncthreads();

    for (int it = 1; it < SS; ++it) {
        float cx = sx[far], cy = sy[far], cz = sz[far];
        unsigned long long cx2 = pack2(-cx, -cx);
        unsigned long long cy2 = pack2(-cy, -cy);
        unsigned long long cz2 = pack2(-cz, -cz);
        float bv = -1.0f; int bi = 0;
#pragma unroll
        for (int jp = 0; jp < 4; jp++) {
            unsigned long long dx2 = add2(X2[jp], cx2);
            unsigned long long dy2 = add2(Y2[jp], cy2);
            unsigned long long dz2 = add2(Z2[jp], cz2);
            unsigned long long d2 = fma2(dz2, dz2, fma2(dy2, dy2, mul2(dx2, dx2)));
            float dlo, dhi;
            unpack2(d2, dlo, dhi);
            float nlo = fminf(Dst[2 * jp], dlo);
            float nhi = fminf(Dst[2 * jp + 1], dhi);
            Dst[2 * jp] = nlo;
            Dst[2 * jp + 1] = nhi;
            if (nlo > bv) { bv = nlo; bi = 2 * jp * 1024 + t; }
            if (nhi > bv) { bv = nhi; bi = (2 * jp + 1) * 1024 + t; }
        }
        unsigned vb = __float_as_uint(bv);
        unsigned m1 = __reduce_max_sync(0xffffffffu, vb);
        unsigned c1 = (vb == m1) ? (unsigned)bi : 0xffffffffu;
        unsigned i1 = __reduce_min_sync(0xffffffffu, c1);
        if (lane == 0) { bufv[par][w] = m1; bufi[par][w] = i1; }
        __syncthreads();
        unsigned v2 = bufv[par][lane];
        unsigned i2 = bufi[par][lane];
        unsigned m2 = __reduce_max_sync(0xffffffffu, v2);
        unsigned c2 = (v2 == m2) ? i2 : 0xffffffffu;
        far = (int)__reduce_min_sync(0xffffffffu, c2);
        if (t == 0) {
            g_cent[b * SS + it] = far;
            if ((it & 31) == 31) { __threadfence(); atomicExch(&g_prog[b], it); }
        }
        par ^= 1;
    }
}

// ================= role: layer0 on unique points (bids 16..143, no deps) =================
__device__ __forceinline__ void g0_role(const float* __restrict__ points,
                                        const float* __restrict__ W0,
                                        const float* __restrict__ b0,
                                        float* sh, int idx)
{
    float* sW = sh;
    float* sB = sh + 576;
    int t = threadIdx.x;
    for (int i = t; i < 576; i += 1024) sW[i] = W0[i];
    if (t < 64) sB[t] = b0[t];
    __syncthreads();

    int col = idx * 1024 + t;
    float x[DD];
#pragma unroll
    for (int k = 0; k < DD; k++) x[k] = points[(size_t)col * DD + k];
#pragma unroll 8
    for (int r = 0; r < 64; ++r) {
        float acc = 0.0f;
#pragma unroll
        for (int k = 0; k < DD; k++) acc = fmaf(sW[r * DD + k], x[k], acc);
        g_Y0[(size_t)r * NPT + col] = acc + sB[r];
    }
}

// ================= role: ball query (bids 144..655) — spin on fps progress =================
__device__ __forceinline__ void bq_role(const float* __restrict__ xyz,
                                        float* __restrict__ out_newxyz,
                                        float4* sp, int idx)
{
    int g = idx >> 4, b = idx & 15;
    int t = threadIdx.x, warp = t >> 5, lane = t & 31;
    int s = (g << 5) + warp;

    if (t == 0) {
        while (atomicAdd(&g_prog[b], 0) < (g << 5) + 31) __nanosleep(256);
        __threadfence();
    }
    __syncthreads();

    int cidx = g_cent[b * SS + s];
    const float* cp = xyz + ((size_t)b * NN + cidx) * 3;
    float cx = cp[0], cy = cp[1], cz = cp[2];
    float cn2 = fmaf(cz, cz, fmaf(cy, cy, __fmul_rn(cx, cx)));
    if (lane < 3) out_newxyz[(b * SS + s) * 3 + lane] = cp[lane];

    const float R2 = 0.04f;
    float dl = 3.4e38f;
    int   il = 0;

    for (int tile = 0; tile < 4; ++tile) {
        __syncthreads();
        for (int i = t; i < 2048; i += 1024) {
            int gp = tile * 2048 + i;
            const float* pp = xyz + ((size_t)b * NN + gp) * 3;
            float px = pp[0], py = pp[1], pz = pp[2];
            sp[i] = make_float4(px, py, pz, fmaf(pz, pz, fmaf(py, py, __fmul_rn(px, px))));
        }
        __syncthreads();
        for (int chunk = 0; chunk < 64; ++chunk) {
            float4 p = sp[chunk * 32 + lane];
            float dot = fmaf(cz, p.z, fmaf(cy, p.y, __fmul_rn(cx, p.x)));
            float d   = __fsub_rn(__fadd_rn(cn2, p.w), __fmul_rn(2.0f, dot));
            float d31 = __shfl_sync(0xffffffffu, dl, 31);
            unsigned mask = __ballot_sync(0xffffffffu, d <= R2 && d < d31);
            while (mask) {
                int c0 = __ffs(mask) - 1;
                mask &= mask - 1;
                float dc = __shfl_sync(0xffffffffu, d, c0);
                d31 = __shfl_sync(0xffffffffu, dl, 31);
                if (dc < d31) {
                    int pos = __popc(__ballot_sync(0xffffffffu, dl <= dc));
                    float dprev = __shfl_up_sync(0xffffffffu, dl, 1);
                    int   iprev = __shfl_up_sync(0xffffffffu, il, 1);
                    int ic = tile * 2048 + chunk * 32 + c0;
                    if (lane >= pos) {
                        dl = (lane == pos) ? dc : dprev;
                        il = (lane == pos) ? ic : iprev;
                    }
                }
            }
        }
    }

    int first = __shfl_sync(0xffffffffu, il, 0);
    int gi = (dl > R2) ? first : il;
    int col = b * NN + gi;
    g_idx[(b * SS + s) * KK + lane] = col;
    atomicAdd(&g_cnt[col], 1);
}

// ================= fused pipeline kernel (1 block/SM by registers) =================
__global__ __launch_bounds__(1024, 1) void fused_kernel(const float* __restrict__ xyz,
                                                        const float* __restrict__ points,
                                                        float* __restrict__ out_newxyz,
                                                        const float* __restrict__ W0,
                                                        const float* __restrict__ b0)
{
    extern __shared__ float sh[];
    int bid = blockIdx.x;
    if (bid < 16)       fps_role(xyz, sh, bid);
    else if (bid < 144) g0_role(points, W0, b0, sh, bid - 16);
    else                bq_role(xyz, out_newxyz, reinterpret_cast<float4*>(sh), bid - 144);
}

// ---------------- layer0 BN stats (needs final counts; reads Y0) ----------------
__global__ __launch_bounds__(256) void stats0_kernel()
{
    __shared__ float swp[8][64];
    __shared__ float swq[8][64];
    int t = threadIdx.x;
    int col = blockIdx.x * 256 + t;
    int warp = t >> 5, lane = t & 31;
    float cntf = (float)g_cnt[col];

#pragma unroll 8
    for (int r = 0; r < 64; ++r) {
        float y = g_Y0[(size_t)r * NPT + col];
        float ps = cntf * y, pq = cntf * (y * y);
#pragma unroll
        for (int o = 16; o > 0; o >>= 1) {
            ps += __shfl_xor_sync(0xffffffffu, ps, o);
            pq += __shfl_xor_sync(0xffffffffu, pq, o);
        }
        if (lane == 0) { swp[warp][r] = ps; swq[warp][r] = pq; }
    }
    __syncthreads();
    if (t < 64) {
        double a = 0.0, q = 0.0;
#pragma unroll
        for (int wv = 0; wv < 8; wv++) { a += (double)swp[wv][t]; q += (double)swq[wv][t]; }
        g_ps [(size_t)t * NBLKMAX + blockIdx.x] = a;
        g_pss[(size_t)t * NBLKMAX + blockIdx.x] = q;
    }
}

// ---------------- GEMM layers 1/2: warp-uniform-W tiling ----------------
// 256 threads = 8 warps; warp rg owns rows [rg*RW, rg*RW+RW), RW = COUT/8.
// Thread (lane=cg) owns col pairs {2cg,2cg+1} and {2cg+64,2cg+65}.
// W loads are warp-uniform (broadcast, 1 wf); x loads are 2 contiguous LDS.64.
// BN partials via stride-33 padded smem (conflict-free STS.32, no shfl).
// TRANS: stage the 128x128 tile row-major in smem (pad 134), then linear STG.32.
template<int COUT, int LAYER, bool TRANS>
__global__ __launch_bounds__(256) void gemm_kernel(const float* __restrict__ X,
                                                   float* __restrict__ Y,
                                                   const float* __restrict__ W,
                                                   const float* __restrict__ Bv)
{
    constexpr int CIN = 64;
    constexpr int RW  = COUT / 8;
    constexpr int TB  = TRANS ? 128 * 134 : (CIN * COUT + CIN * 128);
    extern __shared__ float sm[];
    float* WsT  = sm;                    // [CIN][COUT]   (aliased by tb when TRANS)
    float* Xs   = sm + CIN * COUT;       // [CIN][128]
    float* sps  = sm + TB;               // [COUT][33]
    float* spq  = sps + COUT * 33;       // [COUT][33]
    float* scnt = spq + COUT * 33;       // [128]

    int t = threadIdx.x;
    int cg = t & 31, rg = t >> 5;
    size_t col0 = (size_t)blockIdx.x * 128;

    for (int i = t; i < CIN * COUT; i += 256) {
        int k = i / COUT, r = i - k * COUT;
        WsT[i] = W[r * CIN + k];
    }
    for (int i = t; i < CIN * 128; i += 256) {
        int c = i >> 7, x = i & 127;
        float v = X[(size_t)c * NPT + col0 + x];
        v = fmaxf(fmaf(g_scl[LAYER - 1][c], v, g_shf[LAYER - 1][c]), 0.0f);
        Xs[i] = v;
    }
    if (t < 128) scnt[t] = (float)g_cnt[col0 + t];
    __syncthreads();

    unsigned long long acc[RW][2];
#pragma unroll
    for (int r = 0; r < RW; r++) { acc[r][0] = 0ull; acc[r][1] = 0ull; }

    const unsigned long long* Xs64 = reinterpret_cast<const unsigned long long*>(Xs);
    const float4* W4 = reinterpret_cast<const float4*>(WsT);
#pragma unroll 8
    for (int k = 0; k < CIN; k++) {
        unsigned long long x0 = Xs64[k * 64 + cg];
        unsigned long long x1 = Xs64[k * 64 + cg + 32];
#pragma unroll
        for (int q = 0; q < RW / 4; q++) {
            float4 wv = W4[k * (COUT / 4) + rg * (RW / 4) + q];   // warp-uniform
            float wa[4] = {wv.x, wv.y, wv.z, wv.w};
#pragma unroll
            for (int m = 0; m < 4; m++) {
                unsigned long long w2 = pack2(wa[m], wa[m]);
                acc[q * 4 + m][0] = fma2(w2, x0, acc[q * 4 + m][0]);
                acc[q * 4 + m][1] = fma2(w2, x1, acc[q * 4 + m][1]);
            }
        }
    }

    if (TRANS) __syncthreads();          // tb aliases WsT/Xs: wait for all k-loops

    float c0 = scnt[2 * cg], c1 = scnt[2 * cg + 1];
    float c2 = scnt[2 * cg + 64], c3 = scnt[2 * cg + 65];
#pragma unroll
    for (int rr = 0; rr < RW; rr++) {
        int r = rg * RW + rr;
        float bb = Bv[r];
        float ya, yb, yc, yd;
        unpack2(acc[rr][0], ya, yb); ya += bb; yb += bb;
        unpack2(acc[rr][1], yc, yd); yc += bb; yd += bb;
        if (!TRANS) {
            *reinterpret_cast<float2*>(Y + (size_t)r * NPT + col0 + 2 * cg)      = make_float2(ya, yb);
            *reinterpret_cast<float2*>(Y + (size_t)r * NPT + col0 + 64 + 2 * cg) = make_float2(yc, yd);
        } else {
            *reinterpret_cast<float2*>(sm + r * 134 + 2 * cg)      = make_float2(ya, yb);
            *reinterpret_cast<float2*>(sm + r * 134 + 64 + 2 * cg) = make_float2(yc, yd);
        }
        float ps = fmaf(c0, ya, fmaf(c1, yb, fmaf(c2, yc, c3 * yd)));
        float pq = fmaf(c0, ya * ya, fmaf(c1, yb * yb, fmaf(c2, yc * yc, c3 * (yd * yd))));
        sps[r * 33 + cg] = ps;
        spq[r * 33 + cg] = pq;
    }
    __syncthreads();
    if (TRANS) {
        float* tb = sm;
        float* yout = Y + col0 * 128;
#pragma unroll 8
        for (int i = 0; i < 64; i++) {
            int e = i * 256 + t;
            yout[e] = tb[(e & 127) * 134 + (e >> 7)];   // linear coalesced STG.32
        }
    }
    if (t < COUT) {
        double a = 0.0, q = 0.0;
#pragma unroll
        for (int l = 0; l < 32; l++) { a += (double)sps[t * 33 + l]; q += (double)spq[t * 33 + l]; }
        g_ps [(size_t)t * NBLKMAX + blockIdx.x] = a;
        g_pss[(size_t)t * NBLKMAX + blockIdx.x] = q;
    }
}

// ---------------- BN finalize ----------------
__global__ __launch_bounds__(128) void finalize_kernel(const float* __restrict__ gamma,
                                                       const float* __restrict__ beta,
                                                       int layer, int nblk)
{
    int c = blockIdx.x, t = threadIdx.x;
    __shared__ double sh1[128], sh2[128];
    double a = 0.0, q = 0.0;
    for (int i = t; i < nblk; i += 128) {
        a += g_ps [(size_t)c * NBLKMAX + i];
        q += g_pss[(size_t)c * NBLKMAX + i];
    }
    sh1[t] = a; sh2[t] = q;
    __syncthreads();
    for (int o = 64; o > 0; o >>= 1) {
        if (t < o) { sh1[t] += sh1[t + o]; sh2[t] += sh2[t + o]; }
        __syncthreads();
    }
    if (t == 0) {
        double mean = sh1[0] / MCOLD;
        double var  = sh2[0] / MCOLD - mean * mean;
        float sc = gamma[c] * rsqrtf((float)var + 1e-5f);
        g_scl[layer][c] = sc;
        g_shf[layer][c] = beta[c] - (float)mean * sc;
    }
}

// ---------------- final: gather-max over 32 idx cols + BN2 affine + relu ------------
__global__ __launch_bounds__(256) void final_kernel(float* __restrict__ out)
{
    int warp = threadIdx.x >> 5, lane = threadIdx.x & 31;
    int cent = blockIdx.x * 8 + warp;
    int myidx = g_idx[cent * KK + lane];
    float4 mx = make_float4(-3.4e38f, -3.4e38f, -3.4e38f, -3.4e38f);
#pragma unroll
    for (int j = 0; j < KK; j++) {
        int col = __shfl_sync(0xffffffffu, myidx, j);
        float4 v = *reinterpret_cast<const float4*>(g_Y2T + (size_t)col * 128 + lane * 4);
        mx.x = fmaxf(mx.x, v.x);
        mx.y = fmaxf(mx.y, v.y);
        mx.z = fmaxf(mx.z, v.z);
        mx.w = fmaxf(mx.w, v.w);
    }
    int c0 = lane * 4;
    float4 o;
    o.x = fmaxf(fmaf(g_scl[2][c0 + 0], mx.x, g_shf[2][c0 + 0]), 0.0f);
    o.y = fmaxf(fmaf(g_scl[2][c0 + 1], mx.y, g_shf[2][c0 + 1]), 0.0f);
    o.z = fmaxf(fmaf(g_scl[2][c0 + 2], mx.z, g_shf[2][c0 + 2]), 0.0f);
    o.w = fmaxf(fmaf(g_scl[2][c0 + 3], mx.w, g_shf[2][c0 + 3]), 0.0f);
    *reinterpret_cast<float4*>(out + (size_t)cent * 128 + c0) = o;
}

// ---------------- launch ----------------
extern "C" void kernel_launch(void* const* d_in, const int* in_sizes, int n_in,
                              void* d_out, int out_size)
{
    const float* xyz    = (const float*)d_in[0];
    const float* points = (const float*)d_in[1];
    const float* W0 = (const float*)d_in[2];
    const float* b0 = (const float*)d_in[3];
    const float* g0 = (const float*)d_in[4];
    const float* be0 = (const float*)d_in[5];
    const float* W1 = (const float*)d_in[6];
    const float* b1 = (const float*)d_in[7];
    const float* g1 = (const float*)d_in[8];
    const float* be1 = (const float*)d_in[9];
    const float* W2 = (const float*)d_in[10];
    const float* b2 = (const float*)d_in[11];
    const float* g2 = (const float*)d_in[12];
    const float* be2 = (const float*)d_in[13];

    float* out      = (float*)d_out;
    float* out_feat = out + BB * SS * 3;

    float *pY0, *pY1, *pY2T;
    cudaGetSymbolAddress((void**)&pY0, g_Y0);
    cudaGetSymbolAddress((void**)&pY1, g_Y1);
    cudaGetSymbolAddress((void**)&pY2T, g_Y2T);

    // reset counts + progress (fresh every graph replay); 2 pads -> ncu slot #4 = fused
    reset_kernel<<<NPT / 256, 256>>>();
    pad_kernel<<<1, 32>>>();
    pad_kernel<<<1, 32>>>();

    // fused fps + gemm0(Y0) + ballquery pipeline (96KB smem, 1 block/SM via regs)
    const int FUSED_SMEM = 3 * NN * 4;
    cudaFuncSetAttribute(fused_kernel, cudaFuncAttributeMaxDynamicSharedMemorySize, FUSED_SMEM);
    fused_kernel<<<16 + 128 + 512, 1024, FUSED_SMEM>>>(xyz, points, out, W0, b0);

    // layer0 count-weighted BN stats (reads Y0), then finalize
    stats0_kernel<<<NPT / 256, 256>>>();
    finalize_kernel<<<64, 128>>>(g0, be0, 0, NPT / 256);

    // layer 1: 64 -> 64  (row-major out)
    {
        size_t smem = (size_t)(64 * 64 + 64 * 128 + 2 * 64 * 33 + 128) * 4;
        cudaFuncSetAttribute(gemm_kernel<64, 1, false>, cudaFuncAttributeMaxDynamicSharedMemorySize, (int)smem);
        gemm_kernel<64, 1, false><<<NPT / 128, 256, smem>>>(pY0, pY1, W1, b1);
        finalize_kernel<<<64, 128>>>(g1, be1, 1, NPT / 128);
    }
    // layer 2: 64 -> 128, column-major output via smem transpose
    {
        size_t smem = (size_t)(128 * 134 + 2 * 128 * 33 + 128) * 4;
        cudaFuncSetAttribute(gemm_kernel<128, 2, true>, cudaFuncAttributeMaxDynamicSharedMemorySize, (int)smem);
        gemm_kernel<128, 2, true><<<NPT / 128, 256, smem>>>(pY1, pY2T, W2, b2);
        finalize_kernel<<<128, 128>>>(g2, be2, 2, NPT / 128);
    }
    // gather-max + BN2 + relu -> feature output
    final_kernel<<<(BB * SS) / 8, 256>>>(out_feat);
}